// round 6
// baseline (speedup 1.0000x reference)
#include <cuda_runtime.h>
#include <cuda_bf16.h>
#include <cstdint>

#define G    64
#define FOLD 256
#define HID  128
#define TM   256    // rows per tile
#define NTHR 512

// Scratch (device globals).
__device__ float g_num[3 * G * FOLD];
__device__ float g_den[3 * G];
__device__ __align__(16) __nv_bfloat16 g_w1bf[3 * FOLD * HID];

// Smem layout (bytes)
#define OFF_BS    0         // B resident: 256k x 128n bf16, 256B/row = 65536
#define OFF_ACCS  65536     // 64 x 256 f32 = 65536
#define OFF_PART  131072    // 2 x 256 f32  = 2048
#define OFF_ES    133120    // 256 f32      = 1024
#define OFF_SGS   134144    // 256 int      = 1024
#define OFF_DENS  135168    // 64 f32       = 256
#define OFF_B1S   135424    // 128 f32      = 512
#define OFF_W2S   135936    // 128 f32      = 512
#define SMEM_SZ   136448

// ---------------------------------------------------------------------------
__global__ void prep_kernel(const float* __restrict__ pa,
                            const float* __restrict__ la,
                            const float* __restrict__ ca) {
    int i = blockIdx.x * blockDim.x + threadIdx.x;
    if (i < FOLD * HID) {
        g_w1bf[i]                  = __float2bfloat16(pa[i]);
        g_w1bf[FOLD * HID + i]     = __float2bfloat16(la[i]);
        g_w1bf[2 * FOLD * HID + i] = __float2bfloat16(ca[i]);
    }
    if (i < 3 * G * FOLD) g_num[i] = 0.f;
    if (i < 3 * G)        g_den[i] = 0.f;
}

__device__ __forceinline__ uint32_t smem_u32(const void* p) {
    return (uint32_t)__cvta_generic_to_shared(p);
}
__device__ __forceinline__ uint32_t pack_bf16x2(float a, float b) {
    __nv_bfloat162 h = __floats2bfloat162_rn(a, b);
    return *reinterpret_cast<uint32_t*>(&h);
}

// ---------------------------------------------------------------------------
// Fused scores + attention-pool. Persistent 512-thread blocks, m256 tiles.
// B (W1, bf16) resident in smem for the whole kernel.
// A fragments are loaded DIRECTLY from global memory as float2 per thread
// (mma.sync m16n8k16 A layout) and converted to bf16x2 in registers:
// the GEMM mainloop has ZERO block-wide barriers.
__global__ __launch_bounds__(NTHR, 1) void fused_kernel(
    const float* __restrict__ x, int N,
    const int* __restrict__ batch, const int* __restrict__ ci0,
    const int* __restrict__ lb, int indirect, int pool,
    const float* __restrict__ b1, const float* __restrict__ W2,
    const float* __restrict__ b2)
{
    extern __shared__ char smem[];
    char*  Bs   = smem + OFF_BS;
    float* accs = (float*)(smem + OFF_ACCS);
    float* part = (float*)(smem + OFF_PART);
    float* e_s  = (float*)(smem + OFF_ES);
    int*   sg_s = (int*)  (smem + OFF_SGS);
    float* dens = (float*)(smem + OFF_DENS);
    float* b1s  = (float*)(smem + OFF_B1S);
    float* w2s  = (float*)(smem + OFF_W2S);

    const __nv_bfloat16* W1b = g_w1bf + (size_t)pool * (FOLD * HID);

    const int tid    = threadIdx.x;
    const int lane   = tid & 31;
    const int warp   = tid >> 5;
    const int warp_m = warp >> 1;       // 0..7  (m32 groups)
    const int wn     = warp & 1;        // 0..1  (n64 groups)
    const int m0     = warp_m * 32;

    const uint32_t bs_base = smem_u32(Bs);

    // ---- one-time init
    for (int i = tid; i < G * FOLD; i += NTHR) accs[i] = 0.f;
    if (tid < G) dens[tid] = 0.f;
    if (tid < HID) { b1s[tid] = b1[tid]; w2s[tid] = W2[tid]; }
    const float b2v = b2[0];

#pragma unroll
    for (int j = 0; j < 8; j++) {
        int i  = tid + j * NTHR;          // 4096 16B chunks
        int k  = i >> 4;
        int nc = i & 15;
        uint32_t dst = bs_base + k * 256 + ((nc ^ (k & 7)) << 4);
        const char* src = (const char*)W1b + (size_t)i * 16;
        asm volatile("cp.async.cg.shared.global [%0], [%1], 16;" :: "r"(dst), "l"(src));
    }
    asm volatile("cp.async.commit_group;");
    asm volatile("cp.async.wait_group 0;");
    __syncthreads();

    const int ntiles = (N + TM - 1) / TM;
    const int kcol   = (lane & 3) * 2;   // A-frag column offset within k16

    for (int tile = blockIdx.x; tile < ntiles; tile += gridDim.x) {
        const int row0 = tile * TM;

        float acc[2][8][4];
#pragma unroll
        for (int mi = 0; mi < 2; mi++)
#pragma unroll
            for (int ni = 0; ni < 8; ni++)
#pragma unroll
                for (int j = 0; j < 4; j++) acc[mi][ni][j] = 0.f;

        // Per-thread A row pointers (4 row variants: mi*16 + {0,8}).
        const int grow = row0 + m0 + (lane >> 2);
        const float* xr[4];
        bool vr[4];
#pragma unroll
        for (int q = 0; q < 4; q++) {
            int r = grow + q * 8;
            vr[q] = (r < N);
            xr[q] = x + (size_t)(vr[q] ? r : 0) * FOLD;
        }

        // ---- barrier-free GEMM mainloop: 16 k16-steps
#pragma unroll
        for (int kt = 0; kt < 8; kt++) {
#pragma unroll
            for (int ks = 0; ks < 2; ks++) {
                const int c0 = kt * 32 + ks * 16 + kcol;

                // raw A loads (8 x LDG.64)
                float2 raw[8];
#pragma unroll
                for (int q = 0; q < 4; q++) {
                    raw[q * 2]     = vr[q] ? *(const float2*)(xr[q] + c0)
                                           : make_float2(0.f, 0.f);
                    raw[q * 2 + 1] = vr[q] ? *(const float2*)(xr[q] + c0 + 8)
                                           : make_float2(0.f, 0.f);
                }

                // B fragments from resident smem
                uint32_t bf[8][2];
#pragma unroll
                for (int nj = 0; nj < 4; nj++) {
                    int k  = kt * 32 + ks * 16 + (lane & 15);
                    int nc = wn * 8 + nj * 2 + (lane >> 4);
                    uint32_t addr = bs_base + k * 256 + ((nc ^ (k & 7)) << 4);
                    asm volatile(
                        "ldmatrix.sync.aligned.m8n8.x4.trans.shared.b16 {%0,%1,%2,%3}, [%4];"
                        : "=r"(bf[nj*2][0]), "=r"(bf[nj*2][1]),
                          "=r"(bf[nj*2+1][0]), "=r"(bf[nj*2+1][1])
                        : "r"(addr));
                }

                // convert + mma
#pragma unroll
                for (int mi = 0; mi < 2; mi++) {
                    uint32_t a0 = pack_bf16x2(raw[mi*4    ].x, raw[mi*4    ].y);
                    uint32_t a1 = pack_bf16x2(raw[mi*4 + 2].x, raw[mi*4 + 2].y);
                    uint32_t a2 = pack_bf16x2(raw[mi*4 + 1].x, raw[mi*4 + 1].y);
                    uint32_t a3 = pack_bf16x2(raw[mi*4 + 3].x, raw[mi*4 + 3].y);
#pragma unroll
                    for (int ni = 0; ni < 8; ni++)
                        asm volatile(
                            "mma.sync.aligned.m16n8k16.row.col.f32.bf16.bf16.f32 "
                            "{%0,%1,%2,%3}, {%4,%5,%6,%7}, {%8,%9}, {%0,%1,%2,%3};"
                            : "+f"(acc[mi][ni][0]), "+f"(acc[mi][ni][1]),
                              "+f"(acc[mi][ni][2]), "+f"(acc[mi][ni][3])
                            : "r"(a0), "r"(a1), "r"(a2), "r"(a3),
                              "r"(bf[ni][0]), "r"(bf[ni][1]));
                }
            }
        }

        // ---- epilogue: relu + 2nd linear, per-warp n64 partial per row
#pragma unroll
        for (int mi = 0; mi < 2; mi++) {
            float p1 = 0.f, p2 = 0.f;
            const int cb = (lane & 3) * 2;
#pragma unroll
            for (int ni = 0; ni < 8; ni++) {
                int c = wn * 64 + ni * 8 + cb;
                float w0 = w2s[c], w1v = w2s[c + 1];
                float q0 = b1s[c], q1 = b1s[c + 1];
                p1 += fmaxf(acc[mi][ni][0] + q0, 0.f) * w0 + fmaxf(acc[mi][ni][1] + q1, 0.f) * w1v;
                p2 += fmaxf(acc[mi][ni][2] + q0, 0.f) * w0 + fmaxf(acc[mi][ni][3] + q1, 0.f) * w1v;
            }
            p1 += __shfl_xor_sync(0xffffffffu, p1, 1);
            p1 += __shfl_xor_sync(0xffffffffu, p1, 2);
            p2 += __shfl_xor_sync(0xffffffffu, p2, 1);
            p2 += __shfl_xor_sync(0xffffffffu, p2, 2);
            if ((lane & 3) == 0) {
                int rl = m0 + mi * 16 + (lane >> 2);
                part[wn * 256 + rl]     = p1;
                part[wn * 256 + rl + 8] = p2;
            }
        }
        __syncthreads();   // B1: part complete (also orders prior pooling)

        if (tid < TM) {
            int row = row0 + tid;
            if (row < N) {
                float s = part[tid] + part[256 + tid] + b2v;
                float e = expf(s);
                e_s[tid]  = e;
                int sg    = indirect ? __ldg(lb + __ldg(ci0 + row)) : __ldg(batch + row);
                sg_s[tid] = sg;
                atomicAdd(dens + sg, e);
            } else {
                e_s[tid]  = 0.f;
                sg_s[tid] = 0;
            }
        }
        __syncthreads();   // B2: e_s / sg_s ready

        // ---- pooling: col = tid&255; two thread-halves pool two 128-row halves
        const int rows = min(TM, N - row0);
        {
            const int c     = tid & 255;
            const int half  = tid >> 8;
            const int rbeg  = half * 128;
            const int rendl = min(rows, rbeg + 128);
            if (rbeg < rendl) {
                int   cur = sg_s[rbeg];
                float a   = 0.f;
                int r = rbeg;
                for (; r + 16 <= rendl; r += 16) {
                    float xv[16];
#pragma unroll
                    for (int j = 0; j < 16; j++)
                        xv[j] = __ldg(x + (size_t)(row0 + r + j) * FOLD + c);
#pragma unroll
                    for (int j = 0; j < 16; j++) {
                        int   sg = sg_s[r + j];
                        float ev = e_s[r + j];
                        if (sg != cur) { atomicAdd(accs + cur * FOLD + c, a); a = 0.f; cur = sg; }
                        a = fmaf(ev, xv[j], a);
                    }
                }
                for (; r < rendl; ++r) {
                    int   sg = sg_s[r];
                    float ev = e_s[r];
                    float xv = __ldg(x + (size_t)(row0 + r) * FOLD + c);
                    if (sg != cur) { atomicAdd(accs + cur * FOLD + c, a); a = 0.f; cur = sg; }
                    a = fmaf(ev, xv, a);
                }
                atomicAdd(accs + cur * FOLD + c, a);
            }
        }
        // next tile's B1 orders this pooling before part/e_s are overwritten
    }

    __syncthreads();
    float* num = g_num + pool * G * FOLD;
    for (int i = tid; i < G * FOLD; i += NTHR) {
        float v = accs[i];
        if (v != 0.f) atomicAdd(num + i, v);
    }
    if (tid < G && dens[tid] != 0.f) atomicAdd(g_den + pool * G + tid, dens[tid]);
}

// ---------------------------------------------------------------------------
__global__ __launch_bounds__(256) void mlp_kernel(
    const float* __restrict__ W1, const float* __restrict__ b1,
    const float* __restrict__ W2, const float* __restrict__ b2,
    const float* __restrict__ oW, const float* __restrict__ ob,
    float* __restrict__ out)
{
    __shared__ float comb[3 * FOLD];
    __shared__ float h1s[FOLD];
    __shared__ float h2s[HID];
    __shared__ float red[4];

    const int g = blockIdx.x, t = threadIdx.x;

    for (int i = t; i < 3 * FOLD; i += 256) {
        int p = i >> 8, cc = i & 255;
        comb[i] = g_num[(p * G + g) * FOLD + cc] / g_den[p * G + g];
    }
    __syncthreads();

    float h = b1[t];
    for (int k = 0; k < 3 * FOLD; k++)
        h = fmaf(comb[k], W1[(size_t)k * FOLD + t], h);
    h1s[t] = fmaxf(h, 0.f);
    __syncthreads();

    if (t < HID) {
        float h2 = b2[t];
        for (int k = 0; k < FOLD; k++)
            h2 = fmaf(h1s[k], W2[(size_t)k * HID + t], h2);
        h2s[t] = fmaxf(h2, 0.f);
    }
    __syncthreads();

    if (t < HID) {
        float v = h2s[t] * oW[t];
#pragma unroll
        for (int off = 16; off > 0; off >>= 1)
            v += __shfl_down_sync(0xffffffffu, v, off);
        if ((t & 31) == 0) red[t >> 5] = v;
    }
    __syncthreads();
    if (t == 0) out[g] = red[0] + red[1] + red[2] + red[3] + ob[0];
}

// ---------------------------------------------------------------------------
extern "C" void kernel_launch(void* const* d_in, const int* in_sizes, int n_in,
                              void* d_out, int out_size)
{
    const float* rec   = (const float*)d_in[0];
    const float* lig   = (const float*)d_in[1];
    const float* cross = (const float*)d_in[2];
    const int*   cidx  = (const int*)d_in[3];
    const int*   pb    = (const int*)d_in[4];
    const int*   lb    = (const int*)d_in[5];
    const float* paW1 = (const float*)d_in[7];
    const float* pab1 = (const float*)d_in[8];
    const float* paW2 = (const float*)d_in[9];
    const float* pab2 = (const float*)d_in[10];
    const float* laW1 = (const float*)d_in[11];
    const float* lab1 = (const float*)d_in[12];
    const float* laW2 = (const float*)d_in[13];
    const float* lab2 = (const float*)d_in[14];
    const float* caW1 = (const float*)d_in[15];
    const float* cab1 = (const float*)d_in[16];
    const float* caW2 = (const float*)d_in[17];
    const float* cab2 = (const float*)d_in[18];
    const float* mW1  = (const float*)d_in[19];
    const float* mb1  = (const float*)d_in[20];
    const float* mW2  = (const float*)d_in[21];
    const float* mb2  = (const float*)d_in[22];
    const float* oW   = (const float*)d_in[23];
    const float* ob   = (const float*)d_in[24];

    float* out = (float*)d_out;

    const int Np = in_sizes[0] / FOLD;
    const int Nl = in_sizes[1] / FOLD;
    const int Nc = in_sizes[2] / FOLD;

    static bool attr_done = false;
    if (!attr_done) {
        cudaFuncSetAttribute(fused_kernel,
                             cudaFuncAttributeMaxDynamicSharedMemorySize, SMEM_SZ);
        attr_done = true;
    }

    prep_kernel<<<(3 * G * FOLD + 255) / 256, 256>>>(paW1, laW1, caW1);

    const int maxb = 148;
    int gp = min((Np + TM - 1) / TM, maxb);
    int gl = min((Nl + TM - 1) / TM, maxb);
    int gc = min((Nc + TM - 1) / TM, maxb);

    fused_kernel<<<gp, NTHR, SMEM_SZ>>>(rec, Np, pb, nullptr, nullptr, 0, 0,
                                        pab1, paW2, pab2);
    fused_kernel<<<gl, NTHR, SMEM_SZ>>>(lig, Nl, lb, nullptr, nullptr, 0, 1,
                                        lab1, laW2, lab2);
    fused_kernel<<<gc, NTHR, SMEM_SZ>>>(cross, Nc, nullptr, cidx, lb, 1, 2,
                                        cab1, caW2, cab2);

    mlp_kernel<<<G, 256>>>(mW1, mb1, mW2, mb2, oW, ob, out);
}

// round 7
// speedup vs baseline: 1.2084x; 1.2084x over previous
#include <cuda_runtime.h>
#include <cuda_fp16.h>
#include <cstdint>

#define G    64
#define FOLD 256
#define HID  128
#define TM   128   // rows per tile
#define NCH  4     // k-chunks of 64 (K=256)
#define NTHR 256

// Scratch (device globals).
__device__ float g_num[3 * G * FOLD];
__device__ float g_den[3 * G];
__device__ __align__(16) __half g_w1h[3 * FOLD * HID];

// Smem layout (bytes)
#define OFF_AS    0        // A: 128r x 64k f16, 128B/row swizzled = 16384
#define OFF_BS    16384    // B: 64k x 128n f16, 256B/row swizzled = 16384
#define OFF_ACCS  32768    // 64 x 256 f32 = 65536
#define OFF_PART  98304    // 2 x 128 f32  = 1024
#define OFF_ES    99328    // 128 f32      = 512
#define OFF_SGS   99840    // 128 int      = 512
#define OFF_DENS  100352   // 64 f32       = 256
#define OFF_B1S   100608   // 128 f32      = 512
#define OFF_W2S   101120   // 128 f32      = 512
#define SMEM_SZ   101632

// ---------------------------------------------------------------------------
__global__ void prep_kernel(const float* __restrict__ pa,
                            const float* __restrict__ la,
                            const float* __restrict__ ca) {
    int i = blockIdx.x * blockDim.x + threadIdx.x;
    if (i < FOLD * HID) {
        g_w1h[i]                  = __float2half(pa[i]);
        g_w1h[FOLD * HID + i]     = __float2half(la[i]);
        g_w1h[2 * FOLD * HID + i] = __float2half(ca[i]);
    }
    if (i < 3 * G * FOLD) g_num[i] = 0.f;
    if (i < 3 * G)        g_den[i] = 0.f;
}

__device__ __forceinline__ uint32_t smem_u32(const void* p) {
    return (uint32_t)__cvta_generic_to_shared(p);
}
__device__ __forceinline__ uint32_t pack_h16x2(float a, float b) {
    __half2 h = __floats2half2_rn(a, b);
    return *reinterpret_cast<uint32_t*>(&h);
}

// ---------------------------------------------------------------------------
// Fused scores + attention-pool. Persistent blocks, m128 tiles, 2 CTA/SM.
// f16 inputs AND f16 accumulation (halves accumulator registers vs f32).
// A prefetched into registers across chunks; B staged via raw cp.async from
// the pre-converted f16 W1 (L2-resident).
__global__ __launch_bounds__(NTHR, 2) void fused_kernel(
    const float* __restrict__ x, int N,
    const int* __restrict__ batch, const int* __restrict__ ci0,
    const int* __restrict__ lb, int indirect, int pool,
    const float* __restrict__ b1, const float* __restrict__ W2,
    const float* __restrict__ b2)
{
    extern __shared__ char smem[];
    char*  As   = smem + OFF_AS;
    char*  Bs   = smem + OFF_BS;
    float* accs = (float*)(smem + OFF_ACCS);
    float* part = (float*)(smem + OFF_PART);
    float* e_s  = (float*)(smem + OFF_ES);
    int*   sg_s = (int*)  (smem + OFF_SGS);
    float* dens = (float*)(smem + OFF_DENS);
    float* b1s  = (float*)(smem + OFF_B1S);
    float* w2s  = (float*)(smem + OFF_W2S);

    const char* W1h = (const char*)(g_w1h + (size_t)pool * (FOLD * HID));

    const int tid    = threadIdx.x;
    const int lane   = tid & 31;
    const int warp   = tid >> 5;
    const int warp_m = warp >> 1;       // 0..3  (m32 groups)
    const int wn     = warp & 1;        // 0..1  (n64 groups)
    const int m0     = warp_m * 32;

    for (int i = tid; i < G * FOLD; i += NTHR) accs[i] = 0.f;
    if (tid < G) dens[tid] = 0.f;
    if (tid < HID) { b1s[tid] = b1[tid]; w2s[tid] = W2[tid]; }
    const float b2v = b2[0];
    __syncthreads();

    const uint32_t as_base = smem_u32(As);
    const uint32_t bs_base = smem_u32(Bs);
    const int ntiles = (N + TM - 1) / TM;

    for (int tile = blockIdx.x; tile < ntiles; tile += gridDim.x) {
        const int row0 = tile * TM;

        // f16 accumulators: 2 regs per m16n8 tile
        uint32_t accu[2][8][2];
#pragma unroll
        for (int mi = 0; mi < 2; mi++)
#pragma unroll
            for (int ni = 0; ni < 8; ni++) {
                accu[mi][ni][0] = 0u;
                accu[mi][ni][1] = 0u;
            }

        // A raw prefetch registers: 4 chunks x 32B = 8 float4
        float4 araw[8];
        auto lda = [&](int kt) {
#pragma unroll
            for (int i = 0; i < 4; i++) {
                int id = tid + i * 256;      // 1024 16B-chunks
                int r  = id >> 3;
                int kc = id & 7;
                int grow = row0 + r;
                if (grow < N) {
                    const float4* p = (const float4*)(x + (size_t)grow * FOLD + kt * 64 + kc * 8);
                    araw[2 * i]     = p[0];
                    araw[2 * i + 1] = p[1];
                } else {
                    araw[2 * i]     = make_float4(0.f, 0.f, 0.f, 0.f);
                    araw[2 * i + 1] = make_float4(0.f, 0.f, 0.f, 0.f);
                }
            }
        };
        auto sta = [&]() {
#pragma unroll
            for (int i = 0; i < 4; i++) {
                int id = tid + i * 256;
                int r  = id >> 3;
                int kc = id & 7;
                uint4 v;
                v.x = pack_h16x2(araw[2 * i].x,     araw[2 * i].y);
                v.y = pack_h16x2(araw[2 * i].z,     araw[2 * i].w);
                v.z = pack_h16x2(araw[2 * i + 1].x, araw[2 * i + 1].y);
                v.w = pack_h16x2(araw[2 * i + 1].z, araw[2 * i + 1].w);
                *(uint4*)(As + r * 128 + ((kc ^ (r & 7)) << 4)) = v;
            }
        };

        lda(0);   // prologue A prefetch

#pragma unroll 1
        for (int kt = 0; kt < NCH; kt++) {
            __syncthreads();   // mma(kt-1) done reading As/Bs (also orders pooling)

            // B(kt): raw cp.async from f16 W1 (issued first for max overlap)
#pragma unroll
            for (int i = 0; i < 4; i++) {
                int id = tid + i * 256;      // 1024 16B-chunks
                int k  = id >> 4;
                int nc = id & 15;
                uint32_t dst = bs_base + k * 256 + ((nc ^ (k & 7)) << 4);
                const char* src = W1h + (size_t)(kt * 64 + k) * 256 + nc * 16;
                asm volatile("cp.async.cg.shared.global [%0], [%1], 16;"
                             :: "r"(dst), "l"(src));
            }
            asm volatile("cp.async.commit_group;");

            sta();                       // A(kt) from prefetched regs
            if (kt + 1 < NCH) lda(kt + 1);  // A(kt+1) LDG hides under mma

            asm volatile("cp.async.wait_group 0;");
            __syncthreads();             // tiles published

#pragma unroll
            for (int ks = 0; ks < 4; ks++) {
                uint32_t af[2][4];
#pragma unroll
                for (int mi = 0; mi < 2; mi++) {
                    int r  = m0 + mi * 16 + (lane & 7) + ((lane >> 3) & 1) * 8;
                    int kc = ks * 2 + (lane >> 4);
                    uint32_t addr = as_base + r * 128 + ((kc ^ (r & 7)) << 4);
                    asm volatile(
                        "ldmatrix.sync.aligned.m8n8.x4.shared.b16 {%0,%1,%2,%3}, [%4];"
                        : "=r"(af[mi][0]), "=r"(af[mi][1]), "=r"(af[mi][2]), "=r"(af[mi][3])
                        : "r"(addr));
                }
                uint32_t bf[8][2];
#pragma unroll
                for (int nj = 0; nj < 4; nj++) {
                    int k  = ks * 16 + (lane & 15);
                    int nc = wn * 8 + nj * 2 + (lane >> 4);
                    uint32_t addr = bs_base + k * 256 + ((nc ^ (k & 7)) << 4);
                    asm volatile(
                        "ldmatrix.sync.aligned.m8n8.x4.trans.shared.b16 {%0,%1,%2,%3}, [%4];"
                        : "=r"(bf[nj*2][0]), "=r"(bf[nj*2][1]),
                          "=r"(bf[nj*2+1][0]), "=r"(bf[nj*2+1][1])
                        : "r"(addr));
                }
#pragma unroll
                for (int mi = 0; mi < 2; mi++)
#pragma unroll
                    for (int ni = 0; ni < 8; ni++)
                        asm volatile(
                            "mma.sync.aligned.m16n8k16.row.col.f16.f16.f16.f16 "
                            "{%0,%1}, {%2,%3,%4,%5}, {%6,%7}, {%0,%1};"
                            : "+r"(accu[mi][ni][0]), "+r"(accu[mi][ni][1])
                            : "r"(af[mi][0]), "r"(af[mi][1]), "r"(af[mi][2]), "r"(af[mi][3]),
                              "r"(bf[ni][0]), "r"(bf[ni][1]));
            }
        }

        // ---- epilogue: relu + 2nd linear, per-warp n64 partial per row
#pragma unroll
        for (int mi = 0; mi < 2; mi++) {
            float p1 = 0.f, p2 = 0.f;
            const int cb = (lane & 3) * 2;
#pragma unroll
            for (int ni = 0; ni < 8; ni++) {
                int c = wn * 64 + ni * 8 + cb;
                float w0 = w2s[c], w1v = w2s[c + 1];
                float q0 = b1s[c], q1 = b1s[c + 1];
                float2 f0 = __half22float2(*(__half2*)&accu[mi][ni][0]);  // rows r
                float2 f1 = __half22float2(*(__half2*)&accu[mi][ni][1]);  // rows r+8
                p1 += fmaxf(f0.x + q0, 0.f) * w0 + fmaxf(f0.y + q1, 0.f) * w1v;
                p2 += fmaxf(f1.x + q0, 0.f) * w0 + fmaxf(f1.y + q1, 0.f) * w1v;
            }
            p1 += __shfl_xor_sync(0xffffffffu, p1, 1);
            p1 += __shfl_xor_sync(0xffffffffu, p1, 2);
            p2 += __shfl_xor_sync(0xffffffffu, p2, 1);
            p2 += __shfl_xor_sync(0xffffffffu, p2, 2);
            if ((lane & 3) == 0) {
                int rl = m0 + mi * 16 + (lane >> 2);
                part[wn * 128 + rl]     = p1;
                part[wn * 128 + rl + 8] = p2;
            }
        }
        __syncthreads();

        if (tid < TM) {
            int row = row0 + tid;
            if (row < N) {
                float s = part[tid] + part[128 + tid] + b2v;
                e_s[tid]  = __expf(s);
                sg_s[tid] = indirect ? __ldg(lb + __ldg(ci0 + row)) : __ldg(batch + row);
            } else {
                e_s[tid]  = 0.f;
                sg_s[tid] = 0;
            }
        }
        __syncthreads();

        // ---- pooling: thread owns column tid (exclusive -> non-atomic +=)
        const int rows = min(TM, N - row0);
        {
            const int c = tid;
            int   cur = sg_s[0];
            float a   = 0.f;
            int r = 0;
            for (; r + 4 <= rows; r += 4) {
                float xv[4];
#pragma unroll
                for (int j = 0; j < 4; j++)
                    xv[j] = __ldg(x + (size_t)(row0 + r + j) * FOLD + c);
#pragma unroll
                for (int j = 0; j < 4; j++) {
                    int   sg = sg_s[r + j];
                    float ev = e_s[r + j];
                    if (sg != cur) { accs[cur * FOLD + c] += a; a = 0.f; cur = sg; }
                    a = fmaf(ev, xv[j], a);
                }
            }
            for (; r < rows; ++r) {
                int   sg = sg_s[r];
                float ev = e_s[r];
                float xv = __ldg(x + (size_t)(row0 + r) * FOLD + c);
                if (sg != cur) { accs[cur * FOLD + c] += a; a = 0.f; cur = sg; }
                a = fmaf(ev, xv, a);
            }
            accs[cur * FOLD + c] += a;
        }
        // Denominators: 64 threads, masked scan.
        if (tid < G) {
            float d = 0.f;
            for (int r = 0; r < rows; ++r)
                d += (sg_s[r] == tid) ? e_s[r] : 0.f;
            dens[tid] += d;
        }
    }

    __syncthreads();
    float* num = g_num + pool * G * FOLD;
    for (int i = tid; i < G * FOLD; i += NTHR) {
        float v = accs[i];
        if (v != 0.f) atomicAdd(num + i, v);
    }
    if (tid < G && dens[tid] != 0.f) atomicAdd(g_den + pool * G + tid, dens[tid]);
}

// ---------------------------------------------------------------------------
__global__ __launch_bounds__(256) void mlp_kernel(
    const float* __restrict__ W1, const float* __restrict__ b1,
    const float* __restrict__ W2, const float* __restrict__ b2,
    const float* __restrict__ oW, const float* __restrict__ ob,
    float* __restrict__ out)
{
    __shared__ float comb[3 * FOLD];
    __shared__ float h1s[FOLD];
    __shared__ float h2s[HID];
    __shared__ float red[4];

    const int g = blockIdx.x, t = threadIdx.x;

    for (int i = t; i < 3 * FOLD; i += 256) {
        int p = i >> 8, cc = i & 255;
        comb[i] = g_num[(p * G + g) * FOLD + cc] / g_den[p * G + g];
    }
    __syncthreads();

    float h = b1[t];
    for (int k = 0; k < 3 * FOLD; k++)
        h = fmaf(comb[k], W1[(size_t)k * FOLD + t], h);
    h1s[t] = fmaxf(h, 0.f);
    __syncthreads();

    if (t < HID) {
        float h2 = b2[t];
        for (int k = 0; k < FOLD; k++)
            h2 = fmaf(h1s[k], W2[(size_t)k * HID + t], h2);
        h2s[t] = fmaxf(h2, 0.f);
    }
    __syncthreads();

    if (t < HID) {
        float v = h2s[t] * oW[t];
#pragma unroll
        for (int off = 16; off > 0; off >>= 1)
            v += __shfl_down_sync(0xffffffffu, v, off);
        if ((t & 31) == 0) red[t >> 5] = v;
    }
    __syncthreads();
    if (t == 0) out[g] = red[0] + red[1] + red[2] + red[3] + ob[0];
}

// ---------------------------------------------------------------------------
extern "C" void kernel_launch(void* const* d_in, const int* in_sizes, int n_in,
                              void* d_out, int out_size)
{
    const float* rec   = (const float*)d_in[0];
    const float* lig   = (const float*)d_in[1];
    const float* cross = (const float*)d_in[2];
    const int*   cidx  = (const int*)d_in[3];
    const int*   pb    = (const int*)d_in[4];
    const int*   lb    = (const int*)d_in[5];
    const float* paW1 = (const float*)d_in[7];
    const float* pab1 = (const float*)d_in[8];
    const float* paW2 = (const float*)d_in[9];
    const float* pab2 = (const float*)d_in[10];
    const float* laW1 = (const float*)d_in[11];
    const float* lab1 = (const float*)d_in[12];
    const float* laW2 = (const float*)d_in[13];
    const float* lab2 = (const float*)d_in[14];
    const float* caW1 = (const float*)d_in[15];
    const float* cab1 = (const float*)d_in[16];
    const float* caW2 = (const float*)d_in[17];
    const float* cab2 = (const float*)d_in[18];
    const float* mW1  = (const float*)d_in[19];
    const float* mb1  = (const float*)d_in[20];
    const float* mW2  = (const float*)d_in[21];
    const float* mb2  = (const float*)d_in[22];
    const float* oW   = (const float*)d_in[23];
    const float* ob   = (const float*)d_in[24];

    float* out = (float*)d_out;

    const int Np = in_sizes[0] / FOLD;
    const int Nl = in_sizes[1] / FOLD;
    const int Nc = in_sizes[2] / FOLD;

    static bool attr_done = false;
    if (!attr_done) {
        cudaFuncSetAttribute(fused_kernel,
                             cudaFuncAttributeMaxDynamicSharedMemorySize, SMEM_SZ);
        attr_done = true;
    }

    prep_kernel<<<(3 * G * FOLD + 255) / 256, 256>>>(paW1, laW1, caW1);

    const int maxb = 296;   // 2 CTA/SM x 148 SMs
    int gp = min((Np + TM - 1) / TM, maxb);
    int gl = min((Nl + TM - 1) / TM, maxb);
    int gc = min((Nc + TM - 1) / TM, maxb);

    fused_kernel<<<gp, NTHR, SMEM_SZ>>>(rec, Np, pb, nullptr, nullptr, 0, 0,
                                        pab1, paW2, pab2);
    fused_kernel<<<gl, NTHR, SMEM_SZ>>>(lig, Nl, lb, nullptr, nullptr, 0, 1,
                                        lab1, laW2, lab2);
    fused_kernel<<<gc, NTHR, SMEM_SZ>>>(cross, Nc, nullptr, cidx, lb, 1, 2,
                                        cab1, caW2, cab2);

    mlp_kernel<<<G, 256>>>(mW1, mb1, mW2, mb2, oW, ob, out);
}

// round 8
// speedup vs baseline: 1.2114x; 1.0024x over previous
#include <cuda_runtime.h>
#include <cuda_fp16.h>
#include <cstdint>

#define G    64
#define FOLD 256
#define HID  128
#define TM   128   // rows per tile
#define NCH  4     // k-chunks of 64 (K=256)
#define NTHR 256

// Scratch (device globals).
__device__ float g_num[3 * G * FOLD];
__device__ float g_den[3 * G];
__device__ __align__(16) __half g_w1h[3 * FOLD * HID];

// Smem layout (bytes)
#define OFF_AS    0        // A: 128r x 64k f16, 128B/row swizzled = 16384
#define OFF_BS    16384    // B: 64k x 128n f16, 256B/row swizzled = 16384
#define OFF_ACCS  32768    // 64 x 256 f32 = 65536
#define OFF_PART  98304    // 2 x 128 f32  = 1024
#define OFF_ES    99328    // 128 f32      = 512
#define OFF_SGS   99840    // 128 int      = 512
#define OFF_DENS  100352   // 64 f32       = 256
#define OFF_B1S   100608   // 128 f32      = 512
#define OFF_W2S   101120   // 128 f32      = 512
#define SMEM_SZ   101632

// ---------------------------------------------------------------------------
__global__ void prep_kernel(const float* __restrict__ pa,
                            const float* __restrict__ la,
                            const float* __restrict__ ca) {
    int i = blockIdx.x * blockDim.x + threadIdx.x;
    if (i < FOLD * HID) {
        g_w1h[i]                  = __float2half(pa[i]);
        g_w1h[FOLD * HID + i]     = __float2half(la[i]);
        g_w1h[2 * FOLD * HID + i] = __float2half(ca[i]);
    }
    if (i < 3 * G * FOLD) g_num[i] = 0.f;
    if (i < 3 * G)        g_den[i] = 0.f;
}

__device__ __forceinline__ uint32_t smem_u32(const void* p) {
    return (uint32_t)__cvta_generic_to_shared(p);
}
__device__ __forceinline__ uint32_t pack_h16x2(float a, float b) {
    __half2 h = __floats2half2_rn(a, b);
    return *reinterpret_cast<uint32_t*>(&h);
}

// ---------------------------------------------------------------------------
// Fused scores + attention-pool. Persistent blocks, m128 tiles, 2 CTA/SM.
// f16 inputs AND f16 accumulation. A prefetched into registers across chunks;
// B staged via raw cp.async from pre-converted f16 W1 (L2-resident).
// Pooling: 16-row LDG batches (deep MLP) + smem-atomic denominators.
__global__ __launch_bounds__(NTHR, 2) void fused_kernel(
    const float* __restrict__ x, int N,
    const int* __restrict__ batch, const int* __restrict__ ci0,
    const int* __restrict__ lb, int indirect, int pool,
    const float* __restrict__ b1, const float* __restrict__ W2,
    const float* __restrict__ b2)
{
    extern __shared__ char smem[];
    char*  As   = smem + OFF_AS;
    char*  Bs   = smem + OFF_BS;
    float* accs = (float*)(smem + OFF_ACCS);
    float* part = (float*)(smem + OFF_PART);
    float* e_s  = (float*)(smem + OFF_ES);
    int*   sg_s = (int*)  (smem + OFF_SGS);
    float* dens = (float*)(smem + OFF_DENS);
    float* b1s  = (float*)(smem + OFF_B1S);
    float* w2s  = (float*)(smem + OFF_W2S);

    const char* W1h = (const char*)(g_w1h + (size_t)pool * (FOLD * HID));

    const int tid    = threadIdx.x;
    const int lane   = tid & 31;
    const int warp   = tid >> 5;
    const int warp_m = warp >> 1;       // 0..3  (m32 groups)
    const int wn     = warp & 1;        // 0..1  (n64 groups)
    const int m0     = warp_m * 32;

    for (int i = tid; i < G * FOLD; i += NTHR) accs[i] = 0.f;
    if (tid < G) dens[tid] = 0.f;
    if (tid < HID) { b1s[tid] = b1[tid]; w2s[tid] = W2[tid]; }
    const float b2v = b2[0];
    __syncthreads();

    const uint32_t as_base = smem_u32(As);
    const uint32_t bs_base = smem_u32(Bs);
    const int ntiles = (N + TM - 1) / TM;

    for (int tile = blockIdx.x; tile < ntiles; tile += gridDim.x) {
        const int row0 = tile * TM;

        // f16 accumulators: 2 regs per m16n8 tile
        uint32_t accu[2][8][2];
#pragma unroll
        for (int mi = 0; mi < 2; mi++)
#pragma unroll
            for (int ni = 0; ni < 8; ni++) {
                accu[mi][ni][0] = 0u;
                accu[mi][ni][1] = 0u;
            }

        // A raw prefetch registers: 4 chunks x 32B = 8 float4
        float4 araw[8];
        auto lda = [&](int kt) {
#pragma unroll
            for (int i = 0; i < 4; i++) {
                int id = tid + i * 256;      // 1024 16B-chunks
                int r  = id >> 3;
                int kc = id & 7;
                int grow = row0 + r;
                if (grow < N) {
                    const float4* p = (const float4*)(x + (size_t)grow * FOLD + kt * 64 + kc * 8);
                    araw[2 * i]     = p[0];
                    araw[2 * i + 1] = p[1];
                } else {
                    araw[2 * i]     = make_float4(0.f, 0.f, 0.f, 0.f);
                    araw[2 * i + 1] = make_float4(0.f, 0.f, 0.f, 0.f);
                }
            }
        };
        auto sta = [&]() {
#pragma unroll
            for (int i = 0; i < 4; i++) {
                int id = tid + i * 256;
                int r  = id >> 3;
                int kc = id & 7;
                uint4 v;
                v.x = pack_h16x2(araw[2 * i].x,     araw[2 * i].y);
                v.y = pack_h16x2(araw[2 * i].z,     araw[2 * i].w);
                v.z = pack_h16x2(araw[2 * i + 1].x, araw[2 * i + 1].y);
                v.w = pack_h16x2(araw[2 * i + 1].z, araw[2 * i + 1].w);
                *(uint4*)(As + r * 128 + ((kc ^ (r & 7)) << 4)) = v;
            }
        };

        lda(0);   // prologue A prefetch

#pragma unroll 1
        for (int kt = 0; kt < NCH; kt++) {
            __syncthreads();   // mma(kt-1) done reading As/Bs (also orders pooling)

            // B(kt): raw cp.async from f16 W1 (issued first for max overlap)
#pragma unroll
            for (int i = 0; i < 4; i++) {
                int id = tid + i * 256;      // 1024 16B-chunks
                int k  = id >> 4;
                int nc = id & 15;
                uint32_t dst = bs_base + k * 256 + ((nc ^ (k & 7)) << 4);
                const char* src = W1h + (size_t)(kt * 64 + k) * 256 + nc * 16;
                asm volatile("cp.async.cg.shared.global [%0], [%1], 16;"
                             :: "r"(dst), "l"(src));
            }
            asm volatile("cp.async.commit_group;");

            sta();                           // A(kt) from prefetched regs
            if (kt + 1 < NCH) lda(kt + 1);   // A(kt+1) LDG hides under mma

            asm volatile("cp.async.wait_group 0;");
            __syncthreads();                 // tiles published

#pragma unroll
            for (int ks = 0; ks < 4; ks++) {
                uint32_t af[2][4];
#pragma unroll
                for (int mi = 0; mi < 2; mi++) {
                    int r  = m0 + mi * 16 + (lane & 7) + ((lane >> 3) & 1) * 8;
                    int kc = ks * 2 + (lane >> 4);
                    uint32_t addr = as_base + r * 128 + ((kc ^ (r & 7)) << 4);
                    asm volatile(
                        "ldmatrix.sync.aligned.m8n8.x4.shared.b16 {%0,%1,%2,%3}, [%4];"
                        : "=r"(af[mi][0]), "=r"(af[mi][1]), "=r"(af[mi][2]), "=r"(af[mi][3])
                        : "r"(addr));
                }
                uint32_t bf[8][2];
#pragma unroll
                for (int nj = 0; nj < 4; nj++) {
                    int k  = ks * 16 + (lane & 15);
                    int nc = wn * 8 + nj * 2 + (lane >> 4);
                    uint32_t addr = bs_base + k * 256 + ((nc ^ (k & 7)) << 4);
                    asm volatile(
                        "ldmatrix.sync.aligned.m8n8.x4.trans.shared.b16 {%0,%1,%2,%3}, [%4];"
                        : "=r"(bf[nj*2][0]), "=r"(bf[nj*2][1]),
                          "=r"(bf[nj*2+1][0]), "=r"(bf[nj*2+1][1])
                        : "r"(addr));
                }
#pragma unroll
                for (int mi = 0; mi < 2; mi++)
#pragma unroll
                    for (int ni = 0; ni < 8; ni++)
                        asm volatile(
                            "mma.sync.aligned.m16n8k16.row.col.f16.f16.f16.f16 "
                            "{%0,%1}, {%2,%3,%4,%5}, {%6,%7}, {%0,%1};"
                            : "+r"(accu[mi][ni][0]), "+r"(accu[mi][ni][1])
                            : "r"(af[mi][0]), "r"(af[mi][1]), "r"(af[mi][2]), "r"(af[mi][3]),
                              "r"(bf[ni][0]), "r"(bf[ni][1]));
            }
        }

        // ---- epilogue: relu + 2nd linear, per-warp n64 partial per row
#pragma unroll
        for (int mi = 0; mi < 2; mi++) {
            float p1 = 0.f, p2 = 0.f;
            const int cb = (lane & 3) * 2;
#pragma unroll
            for (int ni = 0; ni < 8; ni++) {
                int c = wn * 64 + ni * 8 + cb;
                float w0 = w2s[c], w1v = w2s[c + 1];
                float q0 = b1s[c], q1 = b1s[c + 1];
                float2 f0 = __half22float2(*(__half2*)&accu[mi][ni][0]);  // rows r
                float2 f1 = __half22float2(*(__half2*)&accu[mi][ni][1]);  // rows r+8
                p1 += fmaxf(f0.x + q0, 0.f) * w0 + fmaxf(f0.y + q1, 0.f) * w1v;
                p2 += fmaxf(f1.x + q0, 0.f) * w0 + fmaxf(f1.y + q1, 0.f) * w1v;
            }
            p1 += __shfl_xor_sync(0xffffffffu, p1, 1);
            p1 += __shfl_xor_sync(0xffffffffu, p1, 2);
            p2 += __shfl_xor_sync(0xffffffffu, p2, 1);
            p2 += __shfl_xor_sync(0xffffffffu, p2, 2);
            if ((lane & 3) == 0) {
                int rl = m0 + mi * 16 + (lane >> 2);
                part[wn * 128 + rl]     = p1;
                part[wn * 128 + rl + 8] = p2;
            }
        }
        __syncthreads();

        if (tid < TM) {
            int row = row0 + tid;
            if (row < N) {
                float s = part[tid] + part[128 + tid] + b2v;
                float e = __expf(s);
                int  sg = indirect ? __ldg(lb + __ldg(ci0 + row)) : __ldg(batch + row);
                e_s[tid]  = e;
                sg_s[tid] = sg;
                atomicAdd(dens + sg, e);   // <=2-way contention, smem atomics
            } else {
                e_s[tid]  = 0.f;
                sg_s[tid] = 0;
            }
        }
        __syncthreads();

        // ---- pooling: thread owns column tid (exclusive -> non-atomic +=)
        // 16-row LDG batches: deep memory-level parallelism.
        const int rows = min(TM, N - row0);
        {
            const int c = tid;
            int   cur = sg_s[0];
            float a   = 0.f;
            int r = 0;
            for (; r + 16 <= rows; r += 16) {
                float xv[16];
#pragma unroll
                for (int j = 0; j < 16; j++)
                    xv[j] = __ldg(x + (size_t)(row0 + r + j) * FOLD + c);
#pragma unroll
                for (int j = 0; j < 16; j++) {
                    int   sg = sg_s[r + j];
                    float ev = e_s[r + j];
                    if (sg != cur) { accs[cur * FOLD + c] += a; a = 0.f; cur = sg; }
                    a = fmaf(ev, xv[j], a);
                }
            }
            for (; r < rows; ++r) {
                int   sg = sg_s[r];
                float ev = e_s[r];
                float xv = __ldg(x + (size_t)(row0 + r) * FOLD + c);
                if (sg != cur) { accs[cur * FOLD + c] += a; a = 0.f; cur = sg; }
                a = fmaf(ev, xv, a);
            }
            accs[cur * FOLD + c] += a;
        }
    }

    __syncthreads();
    float* num = g_num + pool * G * FOLD;
    for (int i = tid; i < G * FOLD; i += NTHR) {
        float v = accs[i];
        if (v != 0.f) atomicAdd(num + i, v);
    }
    if (tid < G && dens[tid] != 0.f) atomicAdd(g_den + pool * G + tid, dens[tid]);
}

// ---------------------------------------------------------------------------
__global__ __launch_bounds__(256) void mlp_kernel(
    const float* __restrict__ W1, const float* __restrict__ b1,
    const float* __restrict__ W2, const float* __restrict__ b2,
    const float* __restrict__ oW, const float* __restrict__ ob,
    float* __restrict__ out)
{
    __shared__ float comb[3 * FOLD];
    __shared__ float h1s[FOLD];
    __shared__ float h2s[HID];
    __shared__ float red[4];

    const int g = blockIdx.x, t = threadIdx.x;

    for (int i = t; i < 3 * FOLD; i += 256) {
        int p = i >> 8, cc = i & 255;
        comb[i] = g_num[(p * G + g) * FOLD + cc] / g_den[p * G + g];
    }
    __syncthreads();

    float h = b1[t];
    for (int k = 0; k < 3 * FOLD; k++)
        h = fmaf(comb[k], W1[(size_t)k * FOLD + t], h);
    h1s[t] = fmaxf(h, 0.f);
    __syncthreads();

    if (t < HID) {
        float h2 = b2[t];
        for (int k = 0; k < FOLD; k++)
            h2 = fmaf(h1s[k], W2[(size_t)k * HID + t], h2);
        h2s[t] = fmaxf(h2, 0.f);
    }
    __syncthreads();

    if (t < HID) {
        float v = h2s[t] * oW[t];
#pragma unroll
        for (int off = 16; off > 0; off >>= 1)
            v += __shfl_down_sync(0xffffffffu, v, off);
        if ((t & 31) == 0) red[t >> 5] = v;
    }
    __syncthreads();
    if (t == 0) out[g] = red[0] + red[1] + red[2] + red[3] + ob[0];
}

// ---------------------------------------------------------------------------
extern "C" void kernel_launch(void* const* d_in, const int* in_sizes, int n_in,
                              void* d_out, int out_size)
{
    const float* rec   = (const float*)d_in[0];
    const float* lig   = (const float*)d_in[1];
    const float* cross = (const float*)d_in[2];
    const int*   cidx  = (const int*)d_in[3];
    const int*   pb    = (const int*)d_in[4];
    const int*   lb    = (const int*)d_in[5];
    const float* paW1 = (const float*)d_in[7];
    const float* pab1 = (const float*)d_in[8];
    const float* paW2 = (const float*)d_in[9];
    const float* pab2 = (const float*)d_in[10];
    const float* laW1 = (const float*)d_in[11];
    const float* lab1 = (const float*)d_in[12];
    const float* laW2 = (const float*)d_in[13];
    const float* lab2 = (const float*)d_in[14];
    const float* caW1 = (const float*)d_in[15];
    const float* cab1 = (const float*)d_in[16];
    const float* caW2 = (const float*)d_in[17];
    const float* cab2 = (const float*)d_in[18];
    const float* mW1  = (const float*)d_in[19];
    const float* mb1  = (const float*)d_in[20];
    const float* mW2  = (const float*)d_in[21];
    const float* mb2  = (const float*)d_in[22];
    const float* oW   = (const float*)d_in[23];
    const float* ob   = (const float*)d_in[24];

    float* out = (float*)d_out;

    const int Np = in_sizes[0] / FOLD;
    const int Nl = in_sizes[1] / FOLD;
    const int Nc = in_sizes[2] / FOLD;

    static bool attr_done = false;
    if (!attr_done) {
        cudaFuncSetAttribute(fused_kernel,
                             cudaFuncAttributeMaxDynamicSharedMemorySize, SMEM_SZ);
        attr_done = true;
    }

    prep_kernel<<<(3 * G * FOLD + 255) / 256, 256>>>(paW1, laW1, caW1);

    const int maxb = 296;   // 2 CTA/SM x 148 SMs
    int gp = min((Np + TM - 1) / TM, maxb);
    int gl = min((Nl + TM - 1) / TM, maxb);
    int gc = min((Nc + TM - 1) / TM, maxb);

    fused_kernel<<<gp, NTHR, SMEM_SZ>>>(rec, Np, pb, nullptr, nullptr, 0, 0,
                                        pab1, paW2, pab2);
    fused_kernel<<<gl, NTHR, SMEM_SZ>>>(lig, Nl, lb, nullptr, nullptr, 0, 1,
                                        lab1, laW2, lab2);
    fused_kernel<<<gc, NTHR, SMEM_SZ>>>(cross, Nc, nullptr, cidx, lb, 1, 2,
                                        cab1, caW2, cab2);

    mlp_kernel<<<G, 256>>>(mW1, mb1, mW2, mb2, oW, ob, out);
}